// round 16
// baseline (speedup 1.0000x reference)
#include <cuda_runtime.h>
#include <cuda_bf16.h>
#include <cuda_fp16.h>
#include <math.h>
#include <stdint.h>

#define BB 64
#define SS 512
#define II 1024
#define HH 1024

#define KSPLIT 4                 // scan K-splits (chunk = 256)
#define KCHUNK 256
#define NCTA_SCAN 128            // 32 coltiles (32 cols x 3 gates) x 4 ksplits
#define NTHR_SCAN 256
#define SCAN_THREADS (NCTA_SCAN * NTHR_SCAN)

// ---------------------------------------------------------------------------
// Device globals (no allocation allowed anywhere)
// ---------------------------------------------------------------------------
__device__ float g_xg[3][SS][BB][HH];           // input-side pre-activations
__device__ float g_part[KSPLIT][3][BB][HH];     // recurrent GEMM partials
__device__ __half g_hf[BB * HH];                // h as fp16 (single term)
__device__ __half g_xh[BB * SS * II];           // X as fp16 (single term)
__device__ __half g_wh[3][HH * II];             // W_f/o/c as fp16

// grid barrier: 16 arrival buckets (8 CTAs each); every CTA polls all buckets
__device__ unsigned g_cnt[16];
// per-coltile group flags (4 CTAs per group arrive once per step)
__device__ unsigned g_flag[32];

__device__ __forceinline__ unsigned ld_acq(const unsigned* p) {
    unsigned v;
    asm volatile("ld.acquire.gpu.global.u32 %0, [%1];" : "=r"(v) : "l"(p));
    return v;
}
__device__ __forceinline__ void red_rel_add(unsigned* p, unsigned v) {
    asm volatile("red.release.gpu.global.add.u32 [%0], %1;" :: "l"(p), "r"(v) : "memory");
}

__device__ __forceinline__ void grid_sync(unsigned gen) {
    __syncthreads();
    if (threadIdx.x == 0) red_rel_add(&g_cnt[blockIdx.x & 15], 1u);
    if (threadIdx.x < 16) {
        while (ld_acq(&g_cnt[threadIdx.x]) < 8u * gen) { }
    }
    __syncthreads();
}

__global__ void k_reset() {
    if (threadIdx.x < 16) g_cnt[threadIdx.x] = 0;
    if (threadIdx.x < 32) g_flag[threadIdx.x] = 0;
}

// ---------------------------------------------------------------------------
// fp16 HMMA + ldmatrix + cp.async + helpers
// ---------------------------------------------------------------------------
#define MMAH(d, a0, a1, a2, a3, b0, b1)                                       \
    asm volatile("mma.sync.aligned.m16n8k16.row.col.f32.f16.f16.f32 "         \
        "{%0,%1,%2,%3}, {%4,%5,%6,%7}, {%8,%9}, {%0,%1,%2,%3};"               \
        : "+f"((d)[0]), "+f"((d)[1]), "+f"((d)[2]), "+f"((d)[3])              \
        : "r"(a0), "r"(a1), "r"(a2), "r"(a3), "r"(b0), "r"(b1))

#define LDMX4(r, addr)                                                        \
    asm volatile("ldmatrix.sync.aligned.m8n8.x4.shared.b16 {%0,%1,%2,%3}, [%4];" \
        : "=r"((r)[0]), "=r"((r)[1]), "=r"((r)[2]), "=r"((r)[3]) : "r"(addr))

#define CPASYNC(dst, src) \
    asm volatile("cp.async.cg.shared.global [%0], [%1], 16;" :: "r"(dst), "l"(src) : "memory")
#define CPCOMMIT() asm volatile("cp.async.commit_group;" ::: "memory")
#define CPWAIT(n)  asm volatile("cp.async.wait_group %0;" :: "n"(n) : "memory")

#define BAR_SYNC(id, cnt) \
    asm volatile("bar.sync %0, %1;" :: "r"(id), "r"(cnt) : "memory")

__device__ __forceinline__ uint32_t smem_u32(const void* p) {
    uint32_t a;
    asm("{ .reg .u64 t; cvta.to.shared.u64 t, %1; cvt.u32.u64 %0, t; }" : "=r"(a) : "l"(p));
    return a;
}

__device__ __forceinline__ float fast_sigmoid(float x) {
    return __fdividef(1.0f, 1.0f + __expf(-x));
}
__device__ __forceinline__ float fast_tanh(float x) {
    float ax = fabsf(x);
    float e  = __expf(ax + ax);
    float r  = 1.0f - __fdividef(2.0f, e + 1.0f);
    return copysignf(r, x);
}

// ---------------------------------------------------------------------------
// K0: convert fp32 -> fp16 once. which: 0 = X, 1..3 = W_{f,o,c}
// ---------------------------------------------------------------------------
__global__ __launch_bounds__(256) void k_conv(const float* __restrict__ src,
                                              int which, int n4) {
    __half* d = (which == 0) ? g_xh : g_wh[which - 1];
    int stride = gridDim.x * 256;
    for (int q = blockIdx.x * 256 + threadIdx.x; q < n4; q += stride) {
        float4 v = ((const float4*)src)[q];
        __half2 p0 = __floats2half2_rn(v.x, v.y);
        __half2 p1 = __floats2half2_rn(v.z, v.w);
        ((uint2*)d)[q] = make_uint2(*(uint32_t*)&p0, *(uint32_t*)&p1);
    }
}

// ---------------------------------------------------------------------------
// K1: input-side GEMM, single-term fp16 HMMA, cp.async double-buffered.
// M = 32768, N = 3x1024, K = 1024. CTA 128x128, k-step 32, 8 warps (2m x 4n).
// Dynamic SMEM: 2 stages x 2 arrays x 128 x IPITCH fp16 = 40 KB, 2 CTAs/SM.
// ---------------------------------------------------------------------------
#define IPITCH 40
#define IN_ABYTES (128 * IPITCH * 2)          // one array, one stage: 10240 B
#define IN_STG    (2 * IN_ABYTES)             // stage stride: 20480 B
#define SMEM_IN   (2 * IN_STG)                // 40960 B

__global__ __launch_bounds__(256, 2) void k_ingemm(
    const float* __restrict__ bf, const float* __restrict__ bo, const float* __restrict__ bc)
{
    extern __shared__ char ism[];
    const uint32_t sb = smem_u32(ism);

    const int bm = blockIdx.x;
    const int bn = blockIdx.y;
    const int g  = bn >> 3;
    const int col0 = (bn & 7) << 7;

    const float* bg = (g == 0) ? bf : (g == 1) ? bo : bc;

    const int tid  = threadIdx.x;
    const int wid  = tid >> 5;
    const int lane = tid & 31;
    const int gq   = lane >> 2;
    const int tg   = lane & 3;
    const int wm   = wid >> 2;
    const int wn   = wid & 3;

    const int lr = tid >> 1;
    const int lq = tid & 1;

    const __half* srcs[2] = {
        g_xh + (size_t)(bm * 128 + lr) * II,
        g_wh[g] + (size_t)(col0 + lr) * II
    };
    uint32_t dsts[2][2];
    #pragma unroll
    for (int a = 0; a < 2; a++)
        #pragma unroll
        for (int j = 0; j < 2; j++) {
            int kb = lq * 16 + j * 8;
            dsts[a][j] = sb + a * IN_ABYTES + (lr * IPITCH + kb) * 2;
        }

    const int arow = wm * 64 + (lane & 7) + ((lane >> 3) & 1) * 8;
    const int akc  = ((lane >> 4) & 1) * 8;
    const int brow = wn * 32 + (lane & 7) + ((lane >> 4) & 1) * 8;
    const int bkc  = ((lane >> 3) & 1) * 8;
    uint32_t aBb[4], bBb[2];
    #pragma unroll
    for (int mi = 0; mi < 4; mi++)
        aBb[mi] = sb + 0 * IN_ABYTES + (((arow + mi * 16) * IPITCH) + akc) * 2;
    #pragma unroll
    for (int p = 0; p < 2; p++)
        bBb[p] = sb + 1 * IN_ABYTES + (((brow + p * 16) * IPITCH) + bkc) * 2;

    float acc[4][4][4] = {};

    // prologue: stage k-tile 0 into buffer 0
    #pragma unroll
    for (int a = 0; a < 2; a++)
        #pragma unroll
        for (int j = 0; j < 2; j++)
            CPASYNC(dsts[a][j], srcs[a] + (lq * 16 + j * 8));
    CPCOMMIT();

    for (int kt = 0; kt < 32; kt++) {
        if (kt + 1 < 32) {
            const int k0n = (kt + 1) * 32;
            const uint32_t so = ((kt + 1) & 1) * IN_STG;
            #pragma unroll
            for (int a = 0; a < 2; a++)
                #pragma unroll
                for (int j = 0; j < 2; j++)
                    CPASYNC(dsts[a][j] + so, srcs[a] + k0n + (lq * 16 + j * 8));
            CPCOMMIT();
            CPWAIT(1);
        } else {
            CPWAIT(0);
        }
        __syncthreads();

        const uint32_t stg = (kt & 1) * IN_STG;
        #pragma unroll
        for (int kk = 0; kk < 2; kk++) {
            const uint32_t ko = stg + kk * 32;
            uint32_t a_[4][4];
            #pragma unroll
            for (int mi = 0; mi < 4; mi++)
                LDMX4(a_[mi], aBb[mi] + ko);
            #pragma unroll
            for (int p = 0; p < 2; p++) {
                uint32_t b_[4];
                LDMX4(b_, bBb[p] + ko);
                #pragma unroll
                for (int q = 0; q < 2; q++) {
                    const int ni = p * 2 + q;
                    #pragma unroll
                    for (int mi = 0; mi < 4; mi++)
                        MMAH(acc[mi][ni], a_[mi][0], a_[mi][1], a_[mi][2], a_[mi][3], b_[2*q], b_[2*q+1]);
                }
            }
        }
        __syncthreads();
    }

    #pragma unroll
    for (int mi = 0; mi < 4; mi++) {
        int row0 = bm * 128 + wm * 64 + mi * 16 + gq;
        int b0_ = row0 >> 9,       s0_ = row0 & 511;
        int b1_ = (row0 + 8) >> 9, s1_ = (row0 + 8) & 511;
        #pragma unroll
        for (int ni = 0; ni < 4; ni++) {
            int col = col0 + wn * 32 + ni * 8 + tg * 2;
            float2 bb = {bg[col], bg[col + 1]};
            *(float2*)&g_xg[g][s0_][b0_][col] = make_float2(acc[mi][ni][0] + bb.x, acc[mi][ni][1] + bb.y);
            *(float2*)&g_xg[g][s1_][b1_][col] = make_float2(acc[mi][ni][2] + bb.x, acc[mi][ni][3] + bb.y);
        }
    }
}

// ---------------------------------------------------------------------------
// K2: persistent fp16 HMMA scan (identical to round 11 — at its sync floor).
// ---------------------------------------------------------------------------
#define SPITCH 264
#define OFF_U  0
#define OFF_H  (96 * SPITCH * 2)                 // 50688
#define SMEM_SCAN (OFF_H + 64 * SPITCH * 2)      // 84480

__global__ __launch_bounds__(NTHR_SCAN) void k_scan(
    const float* __restrict__ Uf, const float* __restrict__ Uo, const float* __restrict__ Uc,
    float* __restrict__ out)
{
    extern __shared__ char smem[];
    uint16_t* Usm = (uint16_t*)(smem + OFF_U);     // [urow 0..95][SPITCH]

    const int cta  = blockIdx.x;          // 0..127
    const int ct   = cta >> 2;            // coltile 0..31 (32 cols)
    const int ks   = cta & 3;             // ksplit (K=256)
    const int kbeg = ks * KCHUNK;
    const int colbase = ct * 32;

    const int tid  = threadIdx.x;
    const int wid  = tid >> 5;
    const int lane = tid & 31;
    const int gq   = lane >> 2;
    const int tg   = lane & 3;
    const int mi   = wid & 3;             // 16-batch-row block
    const int nj   = wid >> 2;            // 48-urow block (0..1)
    const int gtid = cta * NTHR_SCAN + tid;

    // ---- convert U slice (3 gates x 32 cols x 256 k) to fp16 SMEM ----
    const float* Usrc[3] = {Uf, Uo, Uc};
    for (int q = tid; q < 96 * 64; q += NTHR_SCAN) {   // float4 slots
        int urow = q >> 6;
        int g    = urow >> 5;
        int r    = urow & 31;
        int k    = (q & 63) << 2;
        float4 u = *(const float4*)(Usrc[g] + (size_t)(colbase + r) * HH + kbeg + k);
        __half2 p0 = __floats2half2_rn(u.x, u.y);
        __half2 p1 = __floats2half2_rn(u.z, u.w);
        *(__half2*)&Usm[urow * SPITCH + k]     = p0;
        *(__half2*)&Usm[urow * SPITCH + k + 2] = p1;
    }

    // ---- zero h (graph replays must not inherit state) ----
    for (int i = gtid; i < BB * HH; i += SCAN_THREADS)
        g_hf[i] = __ushort_as_half((unsigned short)0);

    // ---- per-thread ldmatrix base addresses ----
    const uint32_t sb = smem_u32(smem);
    const int arow = mi * 16 + (lane & 7) + ((lane >> 3) & 1) * 8;
    const int akc  = ((lane >> 4) & 1) * 8;
    const uint32_t aB = sb + OFF_H + (arow * SPITCH + akc) * 2;
    const int brow = (lane & 7) + ((lane >> 4) & 1) * 8;
    const int bkc  = ((lane >> 3) & 1) * 8;
    uint32_t bB[3];
    #pragma unroll
    for (int j = 0; j < 3; j++) {
        int r = nj * 48 + j * 16 + brow;
        bB[j] = sb + OFF_U + (r * SPITCH + bkc) * 2;
    }

    const int b0_ = mi * 16 + gq;
    const int b1_ = b0_ + 8;

    // staging: this warp owns h-rows [rowbase, rowbase+8)
    const int rowbase = mi * 16 + nj * 8;

    // phase B: CTA (ct,ks) owns cols [colbase+ks*8, +8) x all 64 b; c in regs
    const int pb_b   = tid >> 2;
    const int pb_col = colbase + ks * 8 + (tid & 3) * 2;
    float cc0 = 0.0f, cc1 = 0.0f;

    unsigned gen = 1;
    grid_sync(gen++);

    for (int t = 0; t < SS; t++) {
        // ---- stage this pair's h rows (8 rows x 256 fp16) ----
        #pragma unroll
        for (int i = 0; i < 8; i++) {
            int row = rowbase + i;
            const char* sh = (const char*)g_hf + (size_t)row * (HH * 2) + kbeg * 2;
            *(uint4*)(smem + OFF_H + row * (SPITCH * 2) + lane * 16) =
                ((const uint4*)sh)[lane];
        }
        BAR_SYNC(mi + 1, 64);             // pair barrier: warps mi and mi+4

        // ---- HMMA: D[16 b][48 urows] per warp, K=256, single fp16 term ----
        float acc[6][4] = {};
        #pragma unroll 4
        for (int kk = 0; kk < 16; kk++) {
            const uint32_t ko = kk * 32;
            uint32_t a[4];
            LDMX4(a, aB + ko);
            #pragma unroll
            for (int j = 0; j < 3; j++) {
                uint32_t b[4];
                LDMX4(b, bB[j] + ko);
                MMAH(acc[j*2],   a[0], a[1], a[2], a[3], b[0], b[1]);
                MMAH(acc[j*2+1], a[0], a[1], a[2], a[3], b[2], b[3]);
            }
        }

        // ---- write partials: urow -> (gate, col) ----
        #pragma unroll
        for (int idx = 0; idx < 6; idx++) {
            int n    = nj * 48 + idx * 8 + tg * 2;
            int g    = n >> 5;
            int col  = colbase + (n & 31);
            *(float2*)&g_part[ks][g][b0_][col] = make_float2(acc[idx][0], acc[idx][1]);
            *(float2*)&g_part[ks][g][b1_][col] = make_float2(acc[idx][2], acc[idx][3]);
        }
        __syncthreads();                   // all partial stores done CTA-wide
        if (tid == 0) red_rel_add(&g_flag[ct], 1u);

        // ---- prefetch phase-B gate pre-activations (fly during flag wait)
        float2 xf = *(const float2*)&g_xg[0][t][pb_b][pb_col];
        float2 xo = *(const float2*)&g_xg[1][t][pb_b][pb_col];
        float2 xc = *(const float2*)&g_xg[2][t][pb_b][pb_col];

        // ---- group-local wait: all 4 ksplit CTAs of this coltile done ----
        if (tid == 0) {
            while (ld_acq(&g_flag[ct]) < 4u * (unsigned)(t + 1)) { }
        }
        __syncthreads();

        // ---- phase B: reduce 4 ksplits x 3 gates, update c, write h ----
        {
            float pf0 = xf.x, pf1 = xf.y;
            float po0 = xo.x, po1 = xo.y;
            float pc0 = xc.x, pc1 = xc.y;
            #pragma unroll
            for (int k = 0; k < KSPLIT; k++) {
                float2 v;
                v = *(const float2*)&g_part[k][0][pb_b][pb_col];
                pf0 += v.x; pf1 += v.y;
                v = *(const float2*)&g_part[k][1][pb_b][pb_col];
                po0 += v.x; po1 += v.y;
                v = *(const float2*)&g_part[k][2][pb_b][pb_col];
                pc0 += v.x; pc1 += v.y;
            }
            cc0 = fast_sigmoid(pf0) * cc0 + fast_tanh(pc0);
            cc1 = fast_sigmoid(pf1) * cc1 + fast_tanh(pc1);
            float h0 = fast_sigmoid(po0) * cc0;
            float h1 = fast_sigmoid(po1) * cc1;

            *(__half2*)&g_hf[pb_b * HH + pb_col] = __floats2half2_rn(h0, h1);

            *(float2*)&out[((size_t)pb_b * SS + t) * HH + pb_col] = make_float2(h0, h1);
            if (t == SS - 1) {
                float* o2 = out + (size_t)BB * SS * HH;
                *(float2*)&o2[pb_b * HH + pb_col] = make_float2(h0, h1);
                float* o3 = o2 + BB * HH;
                *(float2*)&o3[pb_b * HH + pb_col] = make_float2(cc0, cc1);
            }
        }

        grid_sync(gen++);                  // single global barrier per step
    }
}

extern "C" void kernel_launch(void* const* d_in, const int* in_sizes, int n_in,
                              void* d_out, int out_size) {
    const float* X  = (const float*)d_in[0];
    const float* Wf = (const float*)d_in[1];
    const float* Uf = (const float*)d_in[2];
    const float* bf = (const float*)d_in[3];
    // d_in[4..6] = W_i/U_i/b_i: gate i is computed-but-unused in the reference.
    const float* Wo = (const float*)d_in[7];
    const float* Uo = (const float*)d_in[8];
    const float* bo = (const float*)d_in[9];
    const float* Wc = (const float*)d_in[10];
    const float* Uc = (const float*)d_in[11];
    const float* bc = (const float*)d_in[12];
    float* out = (float*)d_out;

    cudaFuncSetAttribute(k_ingemm, cudaFuncAttributeMaxDynamicSharedMemorySize, SMEM_IN);
    cudaFuncSetAttribute(k_scan, cudaFuncAttributeMaxDynamicSharedMemorySize, SMEM_SCAN);

    k_reset<<<1, 32>>>();
    k_conv<<<4096, 256>>>(X,  0, (BB * SS * II) / 4);
    k_conv<<<1024, 256>>>(Wf, 1, (HH * II) / 4);
    k_conv<<<1024, 256>>>(Wo, 2, (HH * II) / 4);
    k_conv<<<1024, 256>>>(Wc, 3, (HH * II) / 4);
    k_ingemm<<<dim3(256, 24), 256, SMEM_IN>>>(bf, bo, bc);
    k_scan<<<NCTA_SCAN, NTHR_SCAN, SMEM_SCAN>>>(Uf, Uo, Uc, out);
}

// round 17
// speedup vs baseline: 1.0025x; 1.0025x over previous
#include <cuda_runtime.h>
#include <cuda_bf16.h>
#include <cuda_fp16.h>
#include <math.h>
#include <stdint.h>

#define BB 64
#define SS 512
#define II 1024
#define HH 1024

#define KSPLIT 4                 // scan K-splits (chunk = 256)
#define KCHUNK 256
#define NCTA_SCAN 128            // 32 coltiles (32 cols x 3 gates) x 4 ksplits
#define NTHR_SCAN 256
#define SCAN_THREADS (NCTA_SCAN * NTHR_SCAN)

// ---------------------------------------------------------------------------
// Device globals (no allocation allowed anywhere)
// ---------------------------------------------------------------------------
__device__ float g_xg[3][SS][BB][HH];           // input-side pre-activations
__device__ float g_part[KSPLIT][3][BB][HH];     // recurrent GEMM partials
__device__ __half g_hf[BB * HH];                // h as fp16 (single term)
__device__ __half g_xh[BB * SS * II];           // X as fp16 (single term)
__device__ __half g_wh[3][HH * II];             // W_f/o/c as fp16

// grid barrier: 16 arrival buckets (8 CTAs each); every CTA polls all buckets
__device__ unsigned g_cnt[16];
// per-coltile group flags (4 CTAs per group arrive once per step)
__device__ unsigned g_flag[32];

__device__ __forceinline__ unsigned ld_acq(const unsigned* p) {
    unsigned v;
    asm volatile("ld.acquire.gpu.global.u32 %0, [%1];" : "=r"(v) : "l"(p));
    return v;
}
__device__ __forceinline__ void red_rel_add(unsigned* p, unsigned v) {
    asm volatile("red.release.gpu.global.add.u32 [%0], %1;" :: "l"(p), "r"(v) : "memory");
}

__device__ __forceinline__ void grid_sync(unsigned gen) {
    __syncthreads();
    if (threadIdx.x == 0) red_rel_add(&g_cnt[blockIdx.x & 15], 1u);
    if (threadIdx.x < 16) {
        while (ld_acq(&g_cnt[threadIdx.x]) < 8u * gen) { }
    }
    __syncthreads();
}

__global__ void k_reset() {
    if (threadIdx.x < 16) g_cnt[threadIdx.x] = 0;
    if (threadIdx.x < 32) g_flag[threadIdx.x] = 0;
}

// ---------------------------------------------------------------------------
// fp16 HMMA + ldmatrix + cp.async + helpers
// ---------------------------------------------------------------------------
#define MMAH(d, a0, a1, a2, a3, b0, b1)                                       \
    asm volatile("mma.sync.aligned.m16n8k16.row.col.f32.f16.f16.f32 "         \
        "{%0,%1,%2,%3}, {%4,%5,%6,%7}, {%8,%9}, {%0,%1,%2,%3};"               \
        : "+f"((d)[0]), "+f"((d)[1]), "+f"((d)[2]), "+f"((d)[3])              \
        : "r"(a0), "r"(a1), "r"(a2), "r"(a3), "r"(b0), "r"(b1))

#define LDMX4(r, addr)                                                        \
    asm volatile("ldmatrix.sync.aligned.m8n8.x4.shared.b16 {%0,%1,%2,%3}, [%4];" \
        : "=r"((r)[0]), "=r"((r)[1]), "=r"((r)[2]), "=r"((r)[3]) : "r"(addr))

#define CPASYNC(dst, src) \
    asm volatile("cp.async.cg.shared.global [%0], [%1], 16;" :: "r"(dst), "l"(src) : "memory")
#define CPCOMMIT() asm volatile("cp.async.commit_group;" ::: "memory")
#define CPWAIT(n)  asm volatile("cp.async.wait_group %0;" :: "n"(n) : "memory")

#define BAR_SYNC(id, cnt) \
    asm volatile("bar.sync %0, %1;" :: "r"(id), "r"(cnt) : "memory")

__device__ __forceinline__ uint32_t smem_u32(const void* p) {
    uint32_t a;
    asm("{ .reg .u64 t; cvta.to.shared.u64 t, %1; cvt.u32.u64 %0, t; }" : "=r"(a) : "l"(p));
    return a;
}

__device__ __forceinline__ float fast_sigmoid(float x) {
    return __fdividef(1.0f, 1.0f + __expf(-x));
}
__device__ __forceinline__ float fast_tanh(float x) {
    float ax = fabsf(x);
    float e  = __expf(ax + ax);
    float r  = 1.0f - __fdividef(2.0f, e + 1.0f);
    return copysignf(r, x);
}

// ---------------------------------------------------------------------------
// K0: convert fp32 -> fp16 once. which: 0 = X, 1..3 = W_{f,o,c}
// ---------------------------------------------------------------------------
__global__ __launch_bounds__(256) void k_conv(const float* __restrict__ src,
                                              int which, int n4) {
    __half* d = (which == 0) ? g_xh : g_wh[which - 1];
    int stride = gridDim.x * 256;
    for (int q = blockIdx.x * 256 + threadIdx.x; q < n4; q += stride) {
        float4 v = ((const float4*)src)[q];
        __half2 p0 = __floats2half2_rn(v.x, v.y);
        __half2 p1 = __floats2half2_rn(v.z, v.w);
        ((uint2*)d)[q] = make_uint2(*(uint32_t*)&p0, *(uint32_t*)&p1);
    }
}

// ---------------------------------------------------------------------------
// K1: input-side GEMM, single-term fp16 HMMA, cp.async double-buffered.
// M = 32768, N = 3x1024, K = 1024. CTA 128x128, k-step 32, 8 warps (2m x 4n).
// Dynamic SMEM: 2 stages x 2 arrays x 128 x IPITCH fp16 = 40 KB, 2 CTAs/SM.
// ---------------------------------------------------------------------------
#define IPITCH 40
#define IN_ABYTES (128 * IPITCH * 2)          // one array, one stage: 10240 B
#define IN_STG    (2 * IN_ABYTES)             // stage stride: 20480 B
#define SMEM_IN   (2 * IN_STG)                // 40960 B

__global__ __launch_bounds__(256, 2) void k_ingemm(
    const float* __restrict__ bf, const float* __restrict__ bo, const float* __restrict__ bc)
{
    extern __shared__ char ism[];
    const uint32_t sb = smem_u32(ism);

    const int bm = blockIdx.x;
    const int bn = blockIdx.y;
    const int g  = bn >> 3;
    const int col0 = (bn & 7) << 7;

    const float* bg = (g == 0) ? bf : (g == 1) ? bo : bc;

    const int tid  = threadIdx.x;
    const int wid  = tid >> 5;
    const int lane = tid & 31;
    const int gq   = lane >> 2;
    const int tg   = lane & 3;
    const int wm   = wid >> 2;
    const int wn   = wid & 3;

    const int lr = tid >> 1;
    const int lq = tid & 1;

    const __half* srcs[2] = {
        g_xh + (size_t)(bm * 128 + lr) * II,
        g_wh[g] + (size_t)(col0 + lr) * II
    };
    uint32_t dsts[2][2];
    #pragma unroll
    for (int a = 0; a < 2; a++)
        #pragma unroll
        for (int j = 0; j < 2; j++) {
            int kb = lq * 16 + j * 8;
            dsts[a][j] = sb + a * IN_ABYTES + (lr * IPITCH + kb) * 2;
        }

    const int arow = wm * 64 + (lane & 7) + ((lane >> 3) & 1) * 8;
    const int akc  = ((lane >> 4) & 1) * 8;
    const int brow = wn * 32 + (lane & 7) + ((lane >> 4) & 1) * 8;
    const int bkc  = ((lane >> 3) & 1) * 8;
    uint32_t aBb[4], bBb[2];
    #pragma unroll
    for (int mi = 0; mi < 4; mi++)
        aBb[mi] = sb + 0 * IN_ABYTES + (((arow + mi * 16) * IPITCH) + akc) * 2;
    #pragma unroll
    for (int p = 0; p < 2; p++)
        bBb[p] = sb + 1 * IN_ABYTES + (((brow + p * 16) * IPITCH) + bkc) * 2;

    float acc[4][4][4] = {};

    // prologue: stage k-tile 0 into buffer 0
    #pragma unroll
    for (int a = 0; a < 2; a++)
        #pragma unroll
        for (int j = 0; j < 2; j++)
            CPASYNC(dsts[a][j], srcs[a] + (lq * 16 + j * 8));
    CPCOMMIT();

    for (int kt = 0; kt < 32; kt++) {
        if (kt + 1 < 32) {
            const int k0n = (kt + 1) * 32;
            const uint32_t so = ((kt + 1) & 1) * IN_STG;
            #pragma unroll
            for (int a = 0; a < 2; a++)
                #pragma unroll
                for (int j = 0; j < 2; j++)
                    CPASYNC(dsts[a][j] + so, srcs[a] + k0n + (lq * 16 + j * 8));
            CPCOMMIT();
            CPWAIT(1);
        } else {
            CPWAIT(0);
        }
        __syncthreads();

        const uint32_t stg = (kt & 1) * IN_STG;
        #pragma unroll
        for (int kk = 0; kk < 2; kk++) {
            const uint32_t ko = stg + kk * 32;
            uint32_t a_[4][4];
            #pragma unroll
            for (int mi = 0; mi < 4; mi++)
                LDMX4(a_[mi], aBb[mi] + ko);
            #pragma unroll
            for (int p = 0; p < 2; p++) {
                uint32_t b_[4];
                LDMX4(b_, bBb[p] + ko);
                #pragma unroll
                for (int q = 0; q < 2; q++) {
                    const int ni = p * 2 + q;
                    #pragma unroll
                    for (int mi = 0; mi < 4; mi++)
                        MMAH(acc[mi][ni], a_[mi][0], a_[mi][1], a_[mi][2], a_[mi][3], b_[2*q], b_[2*q+1]);
                }
            }
        }
        __syncthreads();
    }

    #pragma unroll
    for (int mi = 0; mi < 4; mi++) {
        int row0 = bm * 128 + wm * 64 + mi * 16 + gq;
        int b0_ = row0 >> 9,       s0_ = row0 & 511;
        int b1_ = (row0 + 8) >> 9, s1_ = (row0 + 8) & 511;
        #pragma unroll
        for (int ni = 0; ni < 4; ni++) {
            int col = col0 + wn * 32 + ni * 8 + tg * 2;
            float2 bb = {bg[col], bg[col + 1]};
            *(float2*)&g_xg[g][s0_][b0_][col] = make_float2(acc[mi][ni][0] + bb.x, acc[mi][ni][1] + bb.y);
            *(float2*)&g_xg[g][s1_][b1_][col] = make_float2(acc[mi][ni][2] + bb.x, acc[mi][ni][3] + bb.y);
        }
    }
}

// ---------------------------------------------------------------------------
// K2: persistent fp16 HMMA scan (identical to round 11 — at its sync floor).
// ---------------------------------------------------------------------------
#define SPITCH 264
#define OFF_U  0
#define OFF_H  (96 * SPITCH * 2)                 // 50688
#define SMEM_SCAN (OFF_H + 64 * SPITCH * 2)      // 84480

__global__ __launch_bounds__(NTHR_SCAN) void k_scan(
    const float* __restrict__ Uf, const float* __restrict__ Uo, const float* __restrict__ Uc,
    float* __restrict__ out)
{
    extern __shared__ char smem[];
    uint16_t* Usm = (uint16_t*)(smem + OFF_U);     // [urow 0..95][SPITCH]

    const int cta  = blockIdx.x;          // 0..127
    const int ct   = cta >> 2;            // coltile 0..31 (32 cols)
    const int ks   = cta & 3;             // ksplit (K=256)
    const int kbeg = ks * KCHUNK;
    const int colbase = ct * 32;

    const int tid  = threadIdx.x;
    const int wid  = tid >> 5;
    const int lane = tid & 31;
    const int gq   = lane >> 2;
    const int tg   = lane & 3;
    const int mi   = wid & 3;             // 16-batch-row block
    const int nj   = wid >> 2;            // 48-urow block (0..1)
    const int gtid = cta * NTHR_SCAN + tid;

    // ---- convert U slice (3 gates x 32 cols x 256 k) to fp16 SMEM ----
    const float* Usrc[3] = {Uf, Uo, Uc};
    for (int q = tid; q < 96 * 64; q += NTHR_SCAN) {   // float4 slots
        int urow = q >> 6;
        int g    = urow >> 5;
        int r    = urow & 31;
        int k    = (q & 63) << 2;
        float4 u = *(const float4*)(Usrc[g] + (size_t)(colbase + r) * HH + kbeg + k);
        __half2 p0 = __floats2half2_rn(u.x, u.y);
        __half2 p1 = __floats2half2_rn(u.z, u.w);
        *(__half2*)&Usm[urow * SPITCH + k]     = p0;
        *(__half2*)&Usm[urow * SPITCH + k + 2] = p1;
    }

    // ---- zero h (graph replays must not inherit state) ----
    for (int i = gtid; i < BB * HH; i += SCAN_THREADS)
        g_hf[i] = __ushort_as_half((unsigned short)0);

    // ---- per-thread ldmatrix base addresses ----
    const uint32_t sb = smem_u32(smem);
    const int arow = mi * 16 + (lane & 7) + ((lane >> 3) & 1) * 8;
    const int akc  = ((lane >> 4) & 1) * 8;
    const uint32_t aB = sb + OFF_H + (arow * SPITCH + akc) * 2;
    const int brow = (lane & 7) + ((lane >> 4) & 1) * 8;
    const int bkc  = ((lane >> 3) & 1) * 8;
    uint32_t bB[3];
    #pragma unroll
    for (int j = 0; j < 3; j++) {
        int r = nj * 48 + j * 16 + brow;
        bB[j] = sb + OFF_U + (r * SPITCH + bkc) * 2;
    }

    const int b0_ = mi * 16 + gq;
    const int b1_ = b0_ + 8;

    // staging: this warp owns h-rows [rowbase, rowbase+8)
    const int rowbase = mi * 16 + nj * 8;

    // phase B: CTA (ct,ks) owns cols [colbase+ks*8, +8) x all 64 b; c in regs
    const int pb_b   = tid >> 2;
    const int pb_col = colbase + ks * 8 + (tid & 3) * 2;
    float cc0 = 0.0f, cc1 = 0.0f;

    unsigned gen = 1;
    grid_sync(gen++);

    for (int t = 0; t < SS; t++) {
        // ---- stage this pair's h rows (8 rows x 256 fp16) ----
        #pragma unroll
        for (int i = 0; i < 8; i++) {
            int row = rowbase + i;
            const char* sh = (const char*)g_hf + (size_t)row * (HH * 2) + kbeg * 2;
            *(uint4*)(smem + OFF_H + row * (SPITCH * 2) + lane * 16) =
                ((const uint4*)sh)[lane];
        }
        BAR_SYNC(mi + 1, 64);             // pair barrier: warps mi and mi+4

        // ---- HMMA: D[16 b][48 urows] per warp, K=256, single fp16 term ----
        float acc[6][4] = {};
        #pragma unroll 4
        for (int kk = 0; kk < 16; kk++) {
            const uint32_t ko = kk * 32;
            uint32_t a[4];
            LDMX4(a, aB + ko);
            #pragma unroll
            for (int j = 0; j < 3; j++) {
                uint32_t b[4];
                LDMX4(b, bB[j] + ko);
                MMAH(acc[j*2],   a[0], a[1], a[2], a[3], b[0], b[1]);
                MMAH(acc[j*2+1], a[0], a[1], a[2], a[3], b[2], b[3]);
            }
        }

        // ---- write partials: urow -> (gate, col) ----
        #pragma unroll
        for (int idx = 0; idx < 6; idx++) {
            int n    = nj * 48 + idx * 8 + tg * 2;
            int g    = n >> 5;
            int col  = colbase + (n & 31);
            *(float2*)&g_part[ks][g][b0_][col] = make_float2(acc[idx][0], acc[idx][1]);
            *(float2*)&g_part[ks][g][b1_][col] = make_float2(acc[idx][2], acc[idx][3]);
        }
        __syncthreads();                   // all partial stores done CTA-wide
        if (tid == 0) red_rel_add(&g_flag[ct], 1u);

        // ---- prefetch phase-B gate pre-activations (fly during flag wait)
        float2 xf = *(const float2*)&g_xg[0][t][pb_b][pb_col];
        float2 xo = *(const float2*)&g_xg[1][t][pb_b][pb_col];
        float2 xc = *(const float2*)&g_xg[2][t][pb_b][pb_col];

        // ---- group-local wait: all 4 ksplit CTAs of this coltile done ----
        if (tid == 0) {
            while (ld_acq(&g_flag[ct]) < 4u * (unsigned)(t + 1)) { }
        }
        __syncthreads();

        // ---- phase B: reduce 4 ksplits x 3 gates, update c, write h ----
        {
            float pf0 = xf.x, pf1 = xf.y;
            float po0 = xo.x, po1 = xo.y;
            float pc0 = xc.x, pc1 = xc.y;
            #pragma unroll
            for (int k = 0; k < KSPLIT; k++) {
                float2 v;
                v = *(const float2*)&g_part[k][0][pb_b][pb_col];
                pf0 += v.x; pf1 += v.y;
                v = *(const float2*)&g_part[k][1][pb_b][pb_col];
                po0 += v.x; po1 += v.y;
                v = *(const float2*)&g_part[k][2][pb_b][pb_col];
                pc0 += v.x; pc1 += v.y;
            }
            cc0 = fast_sigmoid(pf0) * cc0 + fast_tanh(pc0);
            cc1 = fast_sigmoid(pf1) * cc1 + fast_tanh(pc1);
            float h0 = fast_sigmoid(po0) * cc0;
            float h1 = fast_sigmoid(po1) * cc1;

            *(__half2*)&g_hf[pb_b * HH + pb_col] = __floats2half2_rn(h0, h1);

            *(float2*)&out[((size_t)pb_b * SS + t) * HH + pb_col] = make_float2(h0, h1);
            if (t == SS - 1) {
                float* o2 = out + (size_t)BB * SS * HH;
                *(float2*)&o2[pb_b * HH + pb_col] = make_float2(h0, h1);
                float* o3 = o2 + BB * HH;
                *(float2*)&o3[pb_b * HH + pb_col] = make_float2(cc0, cc1);
            }
        }

        grid_sync(gen++);                  // single global barrier per step
    }
}

extern "C" void kernel_launch(void* const* d_in, const int* in_sizes, int n_in,
                              void* d_out, int out_size) {
    const float* X  = (const float*)d_in[0];
    const float* Wf = (const float*)d_in[1];
    const float* Uf = (const float*)d_in[2];
    const float* bf = (const float*)d_in[3];
    // d_in[4..6] = W_i/U_i/b_i: gate i is computed-but-unused in the reference.
    const float* Wo = (const float*)d_in[7];
    const float* Uo = (const float*)d_in[8];
    const float* bo = (const float*)d_in[9];
    const float* Wc = (const float*)d_in[10];
    const float* Uc = (const float*)d_in[11];
    const float* bc = (const float*)d_in[12];
    float* out = (float*)d_out;

    cudaFuncSetAttribute(k_ingemm, cudaFuncAttributeMaxDynamicSharedMemorySize, SMEM_IN);
    cudaFuncSetAttribute(k_scan, cudaFuncAttributeMaxDynamicSharedMemorySize, SMEM_SCAN);

    k_reset<<<1, 32>>>();
    k_conv<<<4096, 256>>>(X,  0, (BB * SS * II) / 4);
    k_conv<<<1024, 256>>>(Wf, 1, (HH * II) / 4);
    k_conv<<<1024, 256>>>(Wo, 2, (HH * II) / 4);
    k_conv<<<1024, 256>>>(Wc, 3, (HH * II) / 4);
    k_ingemm<<<dim3(256, 24), 256, SMEM_IN>>>(bf, bo, bc);
    k_scan<<<NCTA_SCAN, NTHR_SCAN, SMEM_SCAN>>>(Uf, Uo, Uc, out);
}